// round 2
// baseline (speedup 1.0000x reference)
#include <cuda_runtime.h>
#include <cstdint>

#define MM   8192
#define NN   32768
#define KD   1024
#define DIN  1024
#define KTOP 64

// 128MB scratch: W_enc transposed -> rows are encoder columns (contiguous)
__device__ float g_WT[(size_t)NN * KD];
__device__ float g_c0[NN];

// ======================= K0: c0 = b_enc - b_pre @ W_enc =======================
__global__ void k0_bias(const float* __restrict__ b_pre,
                        const float* __restrict__ W_enc,
                        const float* __restrict__ b_enc) {
    int n = blockIdx.x * blockDim.x + threadIdx.x;
    float s = 0.f;
#pragma unroll 4
    for (int k = 0; k < KD; k++)
        s += b_pre[k] * W_enc[(size_t)k * NN + n];
    g_c0[n] = b_enc[n] - s;
}

// ======================= K0t: transpose W_enc -> g_WT =========================
__global__ void k0_transpose(const float* __restrict__ W) {
    __shared__ float tile[32][33];
    int n0 = blockIdx.x * 32, k0 = blockIdx.y * 32;
    int tx = threadIdx.x, ty = threadIdx.y;   // 32 x 8
#pragma unroll
    for (int r = ty; r < 32; r += 8)
        tile[r][tx] = W[(size_t)(k0 + r) * NN + n0 + tx];
    __syncthreads();
#pragma unroll
    for (int r = ty; r < 32; r += 8)
        g_WT[(size_t)(n0 + r) * KD + k0 + tx] = tile[tx][r];
}

// ======================= K1: Z~ = relu(x @ W_enc + c0)  (TF32 mma.sync) =======
#define BM 128
#define BN 128
#define BK 32
#define AS_STR 36
#define BS_STR 136

__device__ __forceinline__ unsigned f2tf(float f) {
    unsigned u; asm("cvt.rna.tf32.f32 %0, %1;" : "=r"(u) : "f"(f)); return u;
}

__global__ void __launch_bounds__(256, 2)
k1_gemm(const float* __restrict__ A, const float* __restrict__ W,
        float* __restrict__ Z) {
    extern __shared__ float sm[];
    float* As = sm;
    float* Bs = sm + 2 * BM * AS_STR;

    const int NT = NN / BN;
    const int GROUP = 16;
    int tile   = blockIdx.x;
    int width  = GROUP * NT;
    int band   = tile / width;
    int inband = tile % width;
    int pid_m  = band * GROUP + (inband % GROUP);
    int pid_n  = inband / GROUP;
    const int mBase = pid_m * BM;
    const int nBase = pid_n * BN;

    int t = threadIdx.x;
    int warp = t >> 5, lane = t & 31;
    int wM = warp & 3, wN = warp >> 2;
    int gid = lane >> 2, tig = lane & 3;

    float acc[2][8][4];
#pragma unroll
    for (int i = 0; i < 2; i++)
#pragma unroll
        for (int j = 0; j < 8; j++)
#pragma unroll
            for (int q = 0; q < 4; q++) acc[i][j][q] = 0.f;

    auto loadA = [&](int st, int k0) {
#pragma unroll
        for (int i = 0; i < 4; i++) {
            int id = t + i * 256;
            int row = id >> 3, kc = (id & 7) << 2;
            const float* src = A + (size_t)(mBase + row) * KD + k0 + kc;
            unsigned dst = (unsigned)__cvta_generic_to_shared(
                &As[st * BM * AS_STR + row * AS_STR + kc]);
            asm volatile("cp.async.cg.shared.global [%0], [%1], 16;\n"
                         :: "r"(dst), "l"(src));
        }
    };
    auto loadB = [&](int st, int k0) {
#pragma unroll
        for (int i = 0; i < 4; i++) {
            int id = t + i * 256;
            int row = id >> 5, nc = (id & 31) << 2;
            const float* src = W + (size_t)(k0 + row) * NN + nBase + nc;
            unsigned dst = (unsigned)__cvta_generic_to_shared(
                &Bs[st * BK * BS_STR + row * BS_STR + nc]);
            asm volatile("cp.async.cg.shared.global [%0], [%1], 16;\n"
                         :: "r"(dst), "l"(src));
        }
    };

    loadA(0, 0); loadB(0, 0);
    asm volatile("cp.async.commit_group;\n");

    const int NKT = KD / BK;
    for (int kt = 0; kt < NKT; kt++) {
        int cur = kt & 1;
        if (kt + 1 < NKT) {
            loadA(cur ^ 1, (kt + 1) * BK);
            loadB(cur ^ 1, (kt + 1) * BK);
            asm volatile("cp.async.commit_group;\n");
            asm volatile("cp.async.wait_group 1;\n");
        } else {
            asm volatile("cp.async.wait_group 0;\n");
        }
        __syncthreads();

        const float* as = &As[cur * BM * AS_STR];
        const float* bs = &Bs[cur * BK * BS_STR];
#pragma unroll
        for (int ks = 0; ks < 4; ks++) {
            int kb = ks * 8;
            unsigned a[2][4];
#pragma unroll
            for (int mi = 0; mi < 2; mi++) {
                int m = wM * 32 + mi * 16 + gid;
                a[mi][0] = f2tf(as[m       * AS_STR + kb + tig]);
                a[mi][1] = f2tf(as[(m + 8) * AS_STR + kb + tig]);
                a[mi][2] = f2tf(as[m       * AS_STR + kb + tig + 4]);
                a[mi][3] = f2tf(as[(m + 8) * AS_STR + kb + tig + 4]);
            }
            unsigned b[8][2];
#pragma unroll
            for (int ni = 0; ni < 8; ni++) {
                int n = wN * 64 + ni * 8 + gid;
                b[ni][0] = f2tf(bs[(kb + tig)     * BS_STR + n]);
                b[ni][1] = f2tf(bs[(kb + tig + 4) * BS_STR + n]);
            }
#pragma unroll
            for (int mi = 0; mi < 2; mi++)
#pragma unroll
                for (int ni = 0; ni < 8; ni++) {
                    asm volatile(
                        "mma.sync.aligned.m16n8k8.row.col.f32.tf32.tf32.f32 "
                        "{%0,%1,%2,%3},{%4,%5,%6,%7},{%8,%9},{%0,%1,%2,%3};\n"
                        : "+f"(acc[mi][ni][0]), "+f"(acc[mi][ni][1]),
                          "+f"(acc[mi][ni][2]), "+f"(acc[mi][ni][3])
                        : "r"(a[mi][0]), "r"(a[mi][1]), "r"(a[mi][2]), "r"(a[mi][3]),
                          "r"(b[ni][0]), "r"(b[ni][1]));
                }
        }
        __syncthreads();
    }

#pragma unroll
    for (int mi = 0; mi < 2; mi++) {
        int row0 = mBase + wM * 32 + mi * 16 + gid;
#pragma unroll
        for (int ni = 0; ni < 8; ni++) {
            int col = nBase + wN * 64 + ni * 8 + tig * 2;
            float c0a = g_c0[col], c0b = g_c0[col + 1];
            float2 v0 = make_float2(fmaxf(acc[mi][ni][0] + c0a, 0.f),
                                    fmaxf(acc[mi][ni][1] + c0b, 0.f));
            float2 v1 = make_float2(fmaxf(acc[mi][ni][2] + c0a, 0.f),
                                    fmaxf(acc[mi][ni][3] + c0b, 0.f));
            *reinterpret_cast<float2*>(&Z[(size_t)row0 * NN + col])       = v0;
            *reinterpret_cast<float2*>(&Z[(size_t)(row0 + 8) * NN + col]) = v1;
        }
    }
}

// ======================= K2: candidates + exact recompute + top-64 ============
#define T2     512
#define SEG    (NN / T2)
#define NBINS  4096
#define CAP2   512
#define MARGIN 2.5e-3f

// smem layout (bytes)
#define SO_ROW   0
#define SO_HIST  131072
#define SO_PART  (SO_HIST + 16384)
#define SO_CANDI (SO_PART + 2048)
#define SO_CANDV (SO_CANDI + 4*CAP2)
#define SO_XS    (SO_CANDV + 4*CAP2)
#define SO_PAIRV (SO_XS + 4096)
#define SO_PAIRI (SO_PAIRV + 256)
#define SO_VARS  (SO_PAIRI + 256)
#define K2_SMEM  (SO_VARS + 64)

__device__ __forceinline__ void twosum(float& s, float& lo, float p) {
    float t  = s + p;
    float bp = t - s;
    float err = (s - (t - bp)) + (p - bp);
    s = t;
    lo += err;
}

__global__ void __launch_bounds__(T2, 1)
k2_topk(const float* __restrict__ X, float* __restrict__ Zio,
        const float* __restrict__ Wd, const float* __restrict__ b_pre,
        const float* __restrict__ b_enc, float* __restrict__ Xh) {
    extern __shared__ unsigned char smraw[];
    float*    rowv  = (float*)(smraw + SO_ROW);
    unsigned* hist  = (unsigned*)(smraw + SO_HIST);
    unsigned* part  = (unsigned*)(smraw + SO_PART);
    int*      candI = (int*)(smraw + SO_CANDI);
    float*    candV = (float*)(smraw + SO_CANDV);
    float*    xs    = (float*)(smraw + SO_XS);
    float*    pairV = (float*)(smraw + SO_PAIRV);
    int*      pairI = (int*)(smraw + SO_PAIRI);
    unsigned* vars  = (unsigned*)(smraw + SO_VARS);
    // vars: 0=candCount 1=found 2=binB

    const int t = threadIdx.x;
    const int row = blockIdx.x;
    float* zg = Zio + (size_t)row * NN;
    const unsigned* ru = (const unsigned*)rowv;

    // load approx row (coalesced float4) + x row (centered)
#pragma unroll
    for (int i = 0; i < 16; i++) {
        int j = i * 2048 + t * 4;
        *reinterpret_cast<float4*>(rowv + j) =
            *reinterpret_cast<const float4*>(zg + j);
    }
    xs[t]       = X[(size_t)row * KD + t]       - b_pre[t];
    xs[t + 512] = X[(size_t)row * KD + t + 512] - b_pre[t + 512];
#pragma unroll
    for (int i = 0; i < NBINS / T2; i++) hist[t + i * T2] = 0;
    if (t < 8) vars[t] = 0;
    if (t < KTOP) { pairV[t] = 0.f; pairI[t] = 0; }
    __syncthreads();

    // 4096-bin histogram of positive float bits (monotonic)
#pragma unroll 4
    for (int i = 0; i < SEG; i++) {
        unsigned u = ru[t + i * T2];
        if (u) atomicAdd(&hist[u >> 19], 1u);
    }
    __syncthreads();

    // suffix counts: find highest bin B with suffix >= KTOP
    {
        int b8 = t * 8;
        unsigned s = 0;
#pragma unroll
        for (int i = 7; i >= 0; i--) s += hist[b8 + i];
        part[t] = s;
        __syncthreads();
        for (int off = 1; off < T2; off <<= 1) {
            unsigned v = (t + off < T2) ? part[t + off] : 0u;
            __syncthreads();
            part[t] += v;
            __syncthreads();
        }
        unsigned run = (t + 1 < T2) ? part[t + 1] : 0u;
        unsigned sufv[9];
        sufv[8] = run;
#pragma unroll
        for (int i = 7; i >= 0; i--) { run += hist[b8 + i]; sufv[i] = run; }
#pragma unroll
        for (int i = 0; i < 8; i++) {
            if (sufv[i] >= KTOP && sufv[i + 1] < KTOP) {
                vars[2] = (unsigned)(b8 + i);
                vars[1] = 1u;
            }
        }
    }
    __syncthreads();

    // candidate threshold with safety margin covering TF32 error (2x ~8e-4)
    float Tc = vars[1] ? (__uint_as_float(vars[2] << 19) - MARGIN) : 0.f;

    // compact candidate indices
    for (int i = 0; i < SEG; i++) {
        unsigned u = ru[t + i * T2];
        if (u && __uint_as_float(u) >= Tc) {
            unsigned p = atomicAdd(&vars[0], 1u);
            if (p < CAP2) candI[p] = t + i * T2;
        }
    }
    __syncthreads();
    int C = (int)vars[0]; if (C > CAP2) C = CAP2;

    // exact recompute of candidate logits: one warp per candidate.
    // fp32 products with FMA-residual capture + TwoSum double-single accum
    {
        int warp = t >> 5, lane = t & 31;
        for (int c = warp; c < C; c += 16) {
            int j = candI[c];
            const float* wt = g_WT + (size_t)j * KD;
            float s = 0.f, lo = 0.f;
#pragma unroll 8
            for (int i = 0; i < 32; i++) {
                int k = i * 32 + lane;
                float a = xs[k];
                float b = wt[k];
                float p = a * b;
                float e = fmaf(a, b, -p);
                twosum(s, lo, p);
                lo += e;
            }
#pragma unroll
            for (int off = 16; off > 0; off >>= 1) {
                float oh = __shfl_down_sync(0xffffffffu, s, off);
                float ol = __shfl_down_sync(0xffffffffu, lo, off);
                twosum(s, lo, oh);
                lo += ol;
            }
            if (lane == 0) {
                twosum(s, lo, b_enc[j]);
                float v = s + lo;
                candV[c] = fmaxf(v, 0.f);
            }
        }
    }
    __syncthreads();

    // exact top-64 among candidates (ties: lowest index first, like top_k)
    for (int ci = t; ci < C; ci += T2) {
        float vi = candV[ci];
        int   ii = candI[ci];
        int g = 0;
        for (int j = 0; j < C; j++) {
            float vj = candV[j];
            g += (vj > vi) || (vj == vi && candI[j] < ii);
        }
        if (g < KTOP) { pairV[g] = vi; pairI[g] = ii; }
    }
    __syncthreads();

    // z_sparse: zero full row, then scatter exact top-64 values
#pragma unroll
    for (int i = 0; i < 16; i++) {
        int j = i * 2048 + t * 4;
        *reinterpret_cast<float4*>(zg + j) = make_float4(0.f, 0.f, 0.f, 0.f);
    }
    __syncthreads();
    if (t < KTOP && pairV[t] != 0.f) zg[pairI[t]] = pairV[t];

    // decode: x_hat[row] = sum val * W_dec[idx,:] + b_pre (fixed order)
    float a0 = 0.f, a1 = 0.f;
#pragma unroll 8
    for (int p = 0; p < KTOP; p++) {
        float v = pairV[p];
        const float* wr = Wd + (size_t)pairI[p] * DIN;
        a0 += v * wr[t];
        a1 += v * wr[t + T2];
    }
    Xh[(size_t)row * DIN + t]      = a0 + b_pre[t];
    Xh[(size_t)row * DIN + t + T2] = a1 + b_pre[t + T2];
}

// ======================= launch ===============================================
extern "C" void kernel_launch(void* const* d_in, const int* in_sizes, int n_in,
                              void* d_out, int out_size) {
    const float* x     = (const float*)d_in[0];
    const float* b_pre = (const float*)d_in[1];
    const float* W_enc = (const float*)d_in[2];
    const float* b_enc = (const float*)d_in[3];
    const float* W_dec = (const float*)d_in[4];

    float* xhat = (float*)d_out;
    float* zsp  = (float*)d_out + (size_t)MM * DIN;

    const int k1_smem = 2 * BM * AS_STR * 4 + 2 * BK * BS_STR * 4;
    cudaFuncSetAttribute(k1_gemm, cudaFuncAttributeMaxDynamicSharedMemorySize, k1_smem);
    cudaFuncSetAttribute(k2_topk, cudaFuncAttributeMaxDynamicSharedMemorySize, K2_SMEM);

    k0_bias<<<NN / 256, 256>>>(b_pre, W_enc, b_enc);
    dim3 tb(32, 8);
    dim3 tg(NN / 32, KD / 32);
    k0_transpose<<<tg, tb>>>(W_enc);
    k1_gemm<<<(MM / BM) * (NN / BN), 256, k1_smem>>>(x, W_enc, zsp);
    k2_topk<<<MM, T2, K2_SMEM>>>(x, zsp, W_dec, b_pre, b_enc, xhat);
}

// round 9
// speedup vs baseline: 1.2241x; 1.2241x over previous
#include <cuda_runtime.h>
#include <cuda_bf16.h>
#include <cstdint>

#define MM   8192
#define NN   32768
#define KD   1024
#define DIN  1024
#define KTOP 64
#define CAP  1024
#define TLO  1.30f
#define MARG 0.04f      // |z~ - z| bound for bf16 GEMM (~30 sigma)

// ---- device scratch ----
__device__ float          g_WT[(size_t)NN * KD];    // W_enc^T fp32 (exact recompute)
__device__ __nv_bfloat16  g_WTbf[(size_t)NN * KD];  // W_enc^T bf16 (GEMM B)
__device__ __nv_bfloat16  g_Abf[(size_t)MM * KD];   // x bf16 (GEMM A)
__device__ float          g_c0[NN];                 // b_enc - b_pre @ W_enc
__device__ unsigned       g_cnt[MM];
__device__ unsigned       g_flag[MM];
__device__ int            g_candI[(size_t)MM * CAP];
__device__ float          g_candV[(size_t)MM * CAP];

// ======================= K0 prepass ==========================================
__global__ void k0_bias(const float* __restrict__ b_pre,
                        const float* __restrict__ W_enc,
                        const float* __restrict__ b_enc) {
    int n = blockIdx.x * blockDim.x + threadIdx.x;
    float s = 0.f;
#pragma unroll 4
    for (int k = 0; k < KD; k++)
        s += b_pre[k] * W_enc[(size_t)k * NN + n];
    g_c0[n] = b_enc[n] - s;
    if (n < MM) { g_cnt[n] = 0u; g_flag[n] = 0u; }
}

__global__ void k0_transpose(const float* __restrict__ W) {
    __shared__ float tile[32][33];
    int n0 = blockIdx.x * 32, k0 = blockIdx.y * 32;
    int tx = threadIdx.x, ty = threadIdx.y;  // 32 x 8
#pragma unroll
    for (int r = ty; r < 32; r += 8)
        tile[r][tx] = W[(size_t)(k0 + r) * NN + n0 + tx];
    __syncthreads();
#pragma unroll
    for (int r = ty; r < 32; r += 8) {
        float v = tile[tx][r];
        size_t o = (size_t)(n0 + r) * KD + k0 + tx;
        g_WT[o]   = v;
        g_WTbf[o] = __float2bfloat16(v);
    }
}

__global__ void k0_conv(const float* __restrict__ X) {
    size_t base = (size_t)blockIdx.x * 1024 + threadIdx.x * 4;
    float4 v = *reinterpret_cast<const float4*>(X + base);
    g_Abf[base + 0] = __float2bfloat16(v.x);
    g_Abf[base + 1] = __float2bfloat16(v.y);
    g_Abf[base + 2] = __float2bfloat16(v.z);
    g_Abf[base + 3] = __float2bfloat16(v.w);
}

// ======================= K1: bf16 mma.sync GEMM + candidate epilogue =========
#define BM 128
#define BN 128
#define BK 64
#define ASTR 72    // padded row stride (bf16 elems): conflict-free frag loads
// smem: 2 bufs x (A 128x72 + B 128x72) bf16
#define K1_SMEM (4 * BM * ASTR * 2)

__global__ void __launch_bounds__(256, 2)
k1_gemm() {
    extern __shared__ __nv_bfloat16 smh[];
    __nv_bfloat16* As = smh;                       // [2][BM][ASTR]
    __nv_bfloat16* Bs = smh + 2 * BM * ASTR;       // [2][BN][ASTR]

    // supertile swizzle: 16 M-tiles per N sweep (A band stays L2-hot)
    const int NT = NN / BN;              // 256
    const int GROUP = 16;
    int tile   = blockIdx.x;
    int width  = GROUP * NT;
    int band   = tile / width;
    int inband = tile % width;
    int pid_m  = band * GROUP + (inband % GROUP);
    int pid_n  = inband / GROUP;
    const int mBase = pid_m * BM;
    const int nBase = pid_n * BN;

    const int t = threadIdx.x;
    const int warp = t >> 5, lane = t & 31;
    const int wM = warp & 3, wN = warp >> 2;    // 4x2 warps, warp tile 32x64
    const int g = lane >> 2, tig = lane & 3;

    const __nv_bfloat16* Ag = g_Abf  + (size_t)mBase * KD;
    const __nv_bfloat16* Bg = g_WTbf + (size_t)nBase * KD;

    float acc[2][8][4];
#pragma unroll
    for (int i = 0; i < 2; i++)
#pragma unroll
        for (int j = 0; j < 8; j++)
#pragma unroll
            for (int q = 0; q < 4; q++) acc[i][j][q] = 0.f;

    auto loadAB = [&](int st, int k0) {
#pragma unroll
        for (int i = 0; i < 4; i++) {           // A: 1024 x 16B
            int id = t + i * 256;
            int row = id >> 3, c = id & 7;
            const __nv_bfloat16* src = Ag + (size_t)row * KD + k0 + c * 8;
            unsigned dst = (unsigned)__cvta_generic_to_shared(
                &As[st * BM * ASTR + row * ASTR + c * 8]);
            asm volatile("cp.async.cg.shared.global [%0], [%1], 16;\n"
                         :: "r"(dst), "l"(src));
        }
#pragma unroll
        for (int i = 0; i < 4; i++) {           // B: 1024 x 16B
            int id = t + i * 256;
            int row = id >> 3, c = id & 7;
            const __nv_bfloat16* src = Bg + (size_t)row * KD + k0 + c * 8;
            unsigned dst = (unsigned)__cvta_generic_to_shared(
                &Bs[st * BM * ASTR + row * ASTR + c * 8]);
            asm volatile("cp.async.cg.shared.global [%0], [%1], 16;\n"
                         :: "r"(dst), "l"(src));
        }
    };

    loadAB(0, 0);
    asm volatile("cp.async.commit_group;\n");

    const int NKT = KD / BK;  // 16
    for (int kt = 0; kt < NKT; kt++) {
        int cur = kt & 1;
        if (kt + 1 < NKT) {
            loadAB(cur ^ 1, (kt + 1) * BK);
            asm volatile("cp.async.commit_group;\n");
            asm volatile("cp.async.wait_group 1;\n");
        } else {
            asm volatile("cp.async.wait_group 0;\n");
        }
        __syncthreads();

        const uint32_t* as = (const uint32_t*)&As[cur * BM * ASTR];
        const uint32_t* bs = (const uint32_t*)&Bs[cur * BM * ASTR];
        // uint32 view: row stride ASTR/2 = 36 words; elem pair k -> word k/2
#pragma unroll
        for (int ks = 0; ks < 4; ks++) {
            int kb = ks * 16;                    // k offset (elems), pairs: kb/2
            int kw = kb >> 1;                    // word offset
            uint32_t a[2][4];
#pragma unroll
            for (int mi = 0; mi < 2; mi++) {
                int m = wM * 32 + mi * 16 + g;
                a[mi][0] = as[m * 36 + kw + tig];
                a[mi][1] = as[(m + 8) * 36 + kw + tig];
                a[mi][2] = as[m * 36 + kw + 4 + tig];
                a[mi][3] = as[(m + 8) * 36 + kw + 4 + tig];
            }
            uint32_t b[8][2];
#pragma unroll
            for (int ni = 0; ni < 8; ni++) {
                int n = wN * 64 + ni * 8 + g;
                b[ni][0] = bs[n * 36 + kw + tig];
                b[ni][1] = bs[n * 36 + kw + 4 + tig];
            }
#pragma unroll
            for (int mi = 0; mi < 2; mi++)
#pragma unroll
                for (int ni = 0; ni < 8; ni++) {
                    asm volatile(
                        "mma.sync.aligned.m16n8k16.row.col.f32.bf16.bf16.f32 "
                        "{%0,%1,%2,%3},{%4,%5,%6,%7},{%8,%9},{%0,%1,%2,%3};\n"
                        : "+f"(acc[mi][ni][0]), "+f"(acc[mi][ni][1]),
                          "+f"(acc[mi][ni][2]), "+f"(acc[mi][ni][3])
                        : "r"(a[mi][0]), "r"(a[mi][1]), "r"(a[mi][2]), "r"(a[mi][3]),
                          "r"(b[ni][0]), "r"(b[ni][1]));
                }
        }
        __syncthreads();
    }

    // epilogue: +c0, relu-threshold, push candidates (no dense Z write)
#pragma unroll
    for (int ni = 0; ni < 8; ni++) {
        int col = nBase + wN * 64 + ni * 8 + tig * 2;
        float c0a = g_c0[col], c0b = g_c0[col + 1];
#pragma unroll
        for (int mi = 0; mi < 2; mi++) {
            int m = mBase + wM * 32 + mi * 16 + g;
            float v0 = acc[mi][ni][0] + c0a;
            float v1 = acc[mi][ni][1] + c0b;
            float v2 = acc[mi][ni][2] + c0a;
            float v3 = acc[mi][ni][3] + c0b;
            if (v0 >= TLO) {
                unsigned p = atomicAdd(&g_cnt[m], 1u);
                if (p < CAP) { g_candI[(size_t)m*CAP+p] = col;   g_candV[(size_t)m*CAP+p] = v0; }
            }
            if (v1 >= TLO) {
                unsigned p = atomicAdd(&g_cnt[m], 1u);
                if (p < CAP) { g_candI[(size_t)m*CAP+p] = col+1; g_candV[(size_t)m*CAP+p] = v1; }
            }
            if (v2 >= TLO) {
                unsigned p = atomicAdd(&g_cnt[m+8], 1u);
                if (p < CAP) { g_candI[(size_t)(m+8)*CAP+p] = col;   g_candV[(size_t)(m+8)*CAP+p] = v2; }
            }
            if (v3 >= TLO) {
                unsigned p = atomicAdd(&g_cnt[m+8], 1u);
                if (p < CAP) { g_candI[(size_t)(m+8)*CAP+p] = col+1; g_candV[(size_t)(m+8)*CAP+p] = v3; }
            }
        }
    }
}

// ======================= K2: refine + exact recompute + top-64 ===============
__device__ __forceinline__ void twosum(float& s, float& lo, float p) {
    float t  = s + p;
    float bp = t - s;
    float err = (s - (t - bp)) + (p - bp);
    s = t;
    lo += err;
}

__global__ void __launch_bounds__(512, 1)
k2_topk(const float* __restrict__ X, float* __restrict__ Zio,
        const float* __restrict__ Wd, const float* __restrict__ b_pre,
        const float* __restrict__ b_enc, float* __restrict__ Xh) {
    __shared__ float xs[KD];
    __shared__ int   cI[CAP];
    __shared__ float cV[CAP];
    __shared__ float eV[CAP];
    __shared__ float pV[KTOP];
    __shared__ int   pI[KTOP];
    __shared__ float sv64a;

    const int t = threadIdx.x;
    const int row = blockIdx.x;

    unsigned cnt = g_cnt[row];
    int C = (cnt > CAP) ? CAP : (int)cnt;

    xs[t]       = X[(size_t)row * KD + t]       - b_pre[t];
    xs[t + 512] = X[(size_t)row * KD + t + 512] - b_pre[t + 512];
    for (int ci = t; ci < C; ci += 512) {
        cI[ci] = g_candI[(size_t)row * CAP + ci];
        cV[ci] = g_candV[(size_t)row * CAP + ci];
    }
    for (int ci = t; ci < CAP; ci += 512) eV[ci] = -1e30f;
    __syncthreads();

    if (cnt > CAP || C < KTOP) { if (t == 0) g_flag[row] = 1u; return; }

    // approx 64th value (unique rank 63 under value/index total order)
    for (int ci = t; ci < C; ci += 512) {
        float vi = cV[ci]; int ii = cI[ci];
        int g = 0;
        for (int j = 0; j < C; j++) {
            float vj = cV[j];
            g += (vj > vi) || (vj == vi && cI[j] < ii);
        }
        if (g == 63) sv64a = vi;
    }
    __syncthreads();
    const float thr2 = sv64a - 2.f * MARG;

    // exact recompute (double-single) for kept candidates, warp per candidate
    {
        int warp = t >> 5, lane = t & 31;
        for (int c = warp; c < C; c += 16) {
            if (cV[c] < thr2) continue;
            const float* wt = g_WT + (size_t)cI[c] * KD;
            float s = 0.f, lo = 0.f;
#pragma unroll 8
            for (int i = 0; i < 32; i++) {
                int k = i * 32 + lane;
                float a = xs[k], b = wt[k];
                float p = a * b;
                float e = fmaf(a, b, -p);
                twosum(s, lo, p);
                lo += e;
            }
#pragma unroll
            for (int off = 16; off > 0; off >>= 1) {
                float oh = __shfl_down_sync(0xffffffffu, s, off);
                float ol = __shfl_down_sync(0xffffffffu, lo, off);
                twosum(s, lo, oh);
                lo += ol;
            }
            if (lane == 0) {
                twosum(s, lo, b_enc[cI[c]]);
                eV[c] = fmaxf(s + lo, 0.f);
            }
        }
    }
    __syncthreads();

    // exact top-64 (ties -> lowest index)
    for (int ci = t; ci < C; ci += 512) {
        float vi = eV[ci];
        if (vi < -1e29f) continue;
        int ii = cI[ci];
        int g = 0;
        for (int j = 0; j < C; j++) {
            float vj = eV[j];
            g += (vj > vi) || (vj == vi && cI[j] < ii);
        }
        if (g < KTOP) { pV[g] = vi; pI[g] = ii; }
    }
    __syncthreads();

    // certify candidate-set completeness
    if (pV[KTOP - 1] < TLO + MARG) { if (t == 0) g_flag[row] = 1u; return; }

    // z_sparse: zero row + scatter
    float* zg = Zio + (size_t)row * NN;
#pragma unroll
    for (int i = 0; i < 16; i++) {
        int j = i * 2048 + t * 4;
        *reinterpret_cast<float4*>(zg + j) = make_float4(0.f, 0.f, 0.f, 0.f);
    }
    __syncthreads();
    if (t < KTOP) zg[pI[t]] = pV[t];

    // decode
    float a0 = 0.f, a1 = 0.f;
#pragma unroll 8
    for (int p = 0; p < KTOP; p++) {
        float v = pV[p];
        const float* wr = Wd + (size_t)pI[p] * DIN;
        a0 += v * wr[t];
        a1 += v * wr[t + 512];
    }
    Xh[(size_t)row * DIN + t]       = a0 + b_pre[t];
    Xh[(size_t)row * DIN + t + 512] = a1 + b_pre[t + 512];
}

// ======================= K3: exact fallback (flagged rows only) ==============
#define K3_SMEM ((NN + KD + 256 + KTOP) * 4 + (256 + KTOP) * 4)

__global__ void __launch_bounds__(256, 1)
k3_fallback(const float* __restrict__ X, float* __restrict__ Zio,
            const float* __restrict__ Wd, const float* __restrict__ b_pre,
            const float* __restrict__ b_enc, float* __restrict__ Xh) {
    const int row = blockIdx.x;
    if (!g_flag[row]) return;

    extern __shared__ float fs[];
    float* zrow = fs;                 // NN
    float* xs   = fs + NN;            // KD
    float* redV = xs + KD;            // 256
    float* fpV  = redV + 256;         // 64
    int*   redI = (int*)(fpV + KTOP); // 256
    int*   fpI  = redI + 256;         // 64

    const int t = threadIdx.x;
    for (int k = t; k < KD; k += 256) xs[k] = X[(size_t)row * KD + k] - b_pre[k];
    __syncthreads();

    for (int j = t; j < NN; j += 256) {
        const float* wt = g_WT + (size_t)j * KD;
        float s = 0.f, lo = 0.f;
        for (int k = 0; k < KD; k++) {
            float p = xs[k] * wt[k];
            float e = fmaf(xs[k], wt[k], -p);
            twosum(s, lo, p);
            lo += e;
        }
        twosum(s, lo, b_enc[j]);
        zrow[j] = fmaxf(s + lo, 0.f);
    }
    __syncthreads();

    for (int it = 0; it < KTOP; it++) {
        float bv = -1.f; int bi = 0;
        for (int j = t; j < NN; j += 256) {
            float v = zrow[j];
            if (v > bv || (v == bv && j < bi)) { bv = v; bi = j; }
        }
        redV[t] = bv; redI[t] = bi;
        __syncthreads();
        for (int off = 128; off > 0; off >>= 1) {
            if (t < off) {
                float ov = redV[t + off]; int oi = redI[t + off];
                if (ov > redV[t] || (ov == redV[t] && oi < redI[t])) {
                    redV[t] = ov; redI[t] = oi;
                }
            }
            __syncthreads();
        }
        if (t == 0) { fpV[it] = redV[0]; fpI[it] = redI[0]; zrow[redI[0]] = -1.f; }
        __syncthreads();
    }

    float* zg = Zio + (size_t)row * NN;
    for (int j = t; j < NN; j += 256) zg[j] = 0.f;
    __syncthreads();
    if (t < KTOP) zg[fpI[t]] = fpV[t];

    for (int o = t; o < DIN; o += 256) {
        float a = 0.f;
        for (int p = 0; p < KTOP; p++)
            a += fpV[p] * Wd[(size_t)fpI[p] * DIN + o];
        Xh[(size_t)row * DIN + o] = a + b_pre[o];
    }
}

// ======================= launch ===============================================
extern "C" void kernel_launch(void* const* d_in, const int* in_sizes, int n_in,
                              void* d_out, int out_size) {
    const float* x     = (const float*)d_in[0];
    const float* b_pre = (const float*)d_in[1];
    const float* W_enc = (const float*)d_in[2];
    const float* b_enc = (const float*)d_in[3];
    const float* W_dec = (const float*)d_in[4];

    float* xhat = (float*)d_out;
    float* zsp  = (float*)d_out + (size_t)MM * DIN;

    cudaFuncSetAttribute(k1_gemm, cudaFuncAttributeMaxDynamicSharedMemorySize, K1_SMEM);
    cudaFuncSetAttribute(k3_fallback, cudaFuncAttributeMaxDynamicSharedMemorySize, K3_SMEM);

    k0_bias<<<NN / 256, 256>>>(b_pre, W_enc, b_enc);
    dim3 tb(32, 8);
    dim3 tg(NN / 32, KD / 32);
    k0_transpose<<<tg, tb>>>(W_enc);
    k0_conv<<<(int)(((size_t)MM * KD) / 1024), 256>>>(x);
    k1_gemm<<<(MM / BM) * (NN / BN), 256, K1_SMEM>>>();
    k2_topk<<<MM, 512>>>(x, zsp, W_dec, b_pre, b_enc, xhat);
    k3_fallback<<<MM, 256, K3_SMEM>>>(x, zsp, W_dec, b_pre, b_enc, xhat);
}